// round 1
// baseline (speedup 1.0000x reference)
#include <cuda_runtime.h>
#include <math.h>

#define K 128
#define E 4096
#define M 512
#define NUM_UPDATE 3
#define THRESHOLD 0.05f
#define ECHUNK 128
#define NCHUNK (E / ECHUNK)   // 32

// ---------------- device scratch (no allocations allowed) ----------------
__device__ float g_qdv[E * K];            // q_kn * dv, per step
__device__ float g_Ic[E];                 // per step
__device__ float g_Zc[E];                 // step-invariant
__device__ float g_u[K];                  // current state
__device__ float g_partial[K * NCHUNK];   // partial sums for s[k]
__device__ int   g_upd[K];                // update mask

// ---------------- init: u0, upd mask, Zc ----------------
__global__ void init_kernel(const float* __restrict__ U,
                            const int* __restrict__ stu_id,
                            const int* __restrict__ kn_id,
                            const float* __restrict__ gamma_c,
                            const float* __restrict__ d,
                            const float* __restrict__ score) {
    int t = blockIdx.x * blockDim.x + threadIdx.x;
    if (t < E) {
        // Zc = sigmoid(-(gamma_c/d)*(sc-0.5)) - 0.5 = 1/(1+exp(x)) - 0.5
        float x = (gamma_c[t] / d[t]) * (score[t] - 0.5f);
        g_Zc[t] = 1.0f / (1.0f + expf(x)) - 0.5f;
    }
    if (blockIdx.x == 0) {
        int tid = threadIdx.x;
        if (tid < K) {
            g_u[tid]   = U[stu_id[0] * K + tid];
            g_upd[tid] = 0;
        }
        __syncthreads();
        if (tid < K) {
            int kn = kn_id[tid];
            if (kn >= 0 && kn < K) g_upd[kn] = 1;
        }
    }
}

// ---------------- per-step prologue: dv, qdv, su, Ic ----------------
// grid = E/8 blocks of 256 threads; warp per e-row
__global__ void pre_kernel(const float* __restrict__ q_kn,
                           const float* __restrict__ d,
                           const float* __restrict__ score,
                           const float* __restrict__ gs,
                           const float* __restrict__ A_emb) {
    __shared__ float s_u[K];
    __shared__ float s_dv[K];
    int tid = threadIdx.x;
    if (tid < K) {
        float u = g_u[tid];
        s_u[tid] = u;
        float dv = u - 0.5f;
        s_dv[tid] = (fabsf(dv) > THRESHOLD) ? dv : 0.0f;
    }
    __syncthreads();

    int w = tid >> 5, l = tid & 31;
    int e = blockIdx.x * 8 + w;
    float su = 0.0f;
#pragma unroll
    for (int i = 0; i < 4; i++) {
        int j = l + i * 32;
        float q = q_kn[(size_t)e * K + j];
        su += q * s_u[j];
        g_qdv[(size_t)e * K + j] = q * s_dv[j];
    }
    su += __shfl_xor_sync(0xFFFFFFFFu, su, 16);
    su += __shfl_xor_sync(0xFFFFFFFFu, su, 8);
    su += __shfl_xor_sync(0xFFFFFFFFu, su, 4);
    su += __shfl_xor_sync(0xFFFFFFFFu, su, 2);
    su += __shfl_xor_sync(0xFFFFFFFFu, su, 1);
    if (l == 0) {
        float t  = score[e] - su / d[e];
        float yc = expf(-t * t);
        float ic = A_emb[3 * e + 0] * (1.0f - gs[2 * e + 0])
                 + A_emb[3 * e + 1] * (1.0f - gs[2 * e + 1])
                 + A_emb[3 * e + 2] * yc;
        // Ic = sigmoid(-ic)
        g_Ic[e] = 1.0f / (1.0f + expf(ic));
    }
}

// ---------------- the big HBM-bound kernel ----------------
// grid = (NCHUNK, K); block = 256 (8 warps); warp handles 16 e-rows.
// For each (k, e): Gsum = B[k,e,:].qdv[e,:] - B[k,e,k]*qdv[e,k]
// then Gkc = sigmoid(-Gsum)-1 ; WK = Ic[e]*(beta1*Gkc + beta2[e]*Zc[e])
// contribution to s[k]: user[k,e]*W[k,e]*WK
__global__ __launch_bounds__(256) void big_kernel(const float* __restrict__ Bm,
                                                  const float* __restrict__ beta1,
                                                  const float* __restrict__ beta2,
                                                  const float* __restrict__ W,
                                                  const float* __restrict__ user) {
    int k     = blockIdx.y;
    int chunk = blockIdx.x;
    int w = threadIdx.x >> 5, l = threadIdx.x & 31;
    __shared__ float warpacc[8];

    int klane = k >> 2, kcomp = k & 3;
    float acc = 0.0f;

#pragma unroll 4
    for (int r = 0; r < 16; ++r) {
        int e = chunk * ECHUNK + w * 16 + r;
        const float4 b4 = *(const float4*)(Bm + (((size_t)k * E + e) * K) + l * 4);
        const float4 q4 = *(const float4*)(g_qdv + (size_t)e * K + l * 4);
        float dot = b4.x * q4.x + b4.y * q4.y + b4.z * q4.z + b4.w * q4.w;
        if (l == klane) {
            float bb = (kcomp == 0) ? b4.x : (kcomp == 1) ? b4.y : (kcomp == 2) ? b4.z : b4.w;
            float qq = (kcomp == 0) ? q4.x : (kcomp == 1) ? q4.y : (kcomp == 2) ? q4.z : q4.w;
            dot -= bb * qq;
        }
        dot += __shfl_xor_sync(0xFFFFFFFFu, dot, 16);
        dot += __shfl_xor_sync(0xFFFFFFFFu, dot, 8);
        dot += __shfl_xor_sync(0xFFFFFFFFu, dot, 4);
        dot += __shfl_xor_sync(0xFFFFFFFFu, dot, 2);
        dot += __shfl_xor_sync(0xFFFFFFFFu, dot, 1);
        if (l == 0) {
            // Gkc = sigmoid(-Gsum) - 1 = 1/(1+exp(Gsum)) - 1
            float gkc = 1.0f / (1.0f + expf(dot)) - 1.0f;
            float wk  = g_Ic[e] * (beta1[k * E + e] * gkc + beta2[e] * g_Zc[e]);
            acc += user[k * E + e] * W[k * E + e] * wk;
        }
    }
    if (l == 0) warpacc[w] = acc;
    __syncthreads();
    if (threadIdx.x == 0) {
        float s = 0.0f;
#pragma unroll
        for (int i = 0; i < 8; i++) s += warpacc[i];
        g_partial[k * NCHUNK + chunk] = s;
    }
}

// ---------------- per-step epilogue: s -> u_new, diff norm, state store ----------------
__global__ void post_kernel(float* __restrict__ out, int step) {
    int k = threadIdx.x;  // 128 threads
    float s = 0.0f;
#pragma unroll
    for (int c = 0; c < NCHUNK; c++) s += g_partial[k * NCHUNK + c];
    float u_old = g_u[k];
    float u_new = 1.0f / (1.0f + expf(s));   // sigmoid(-s)
    float un = g_upd[k] ? u_new : u_old;
    float dd = un - u_old;

    __shared__ float red[K];
    red[k] = dd * dd;
    __syncthreads();
#pragma unroll
    for (int off = 64; off > 0; off >>= 1) {
        if (k < off) red[k] += red[k + off];
        __syncthreads();
    }
    if (k == 0) out[2 * K + M + step] = sqrtf(red[0]);

    g_u[k] = un;
    if (step == NUM_UPDATE - 2) out[K + k] = un;  // state_2nd_last
    if (step == NUM_UPDATE - 1) out[k]     = un;  // state_last
}

// ---------------- final predict ----------------
// grid = M/8 blocks of 256; warp per exercise
__global__ void predict_kernel(const float* __restrict__ q_kn,
                               const float* __restrict__ d,
                               const float* __restrict__ alpha,
                               const float* __restrict__ gamma_e,
                               const int* __restrict__ ex_id,
                               float* __restrict__ out) {
    __shared__ float s_u[K];
    int tid = threadIdx.x;
    if (tid < K) s_u[tid] = g_u[tid];
    __syncthreads();

    int w = tid >> 5, l = tid & 31;
    int m = blockIdx.x * 8 + w;
    int e = ex_id[m];
    float acc = 0.0f;
#pragma unroll
    for (int i = 0; i < 4; i++) {
        int j = l + i * 32;
        acc += q_kn[(size_t)e * K + j] * s_u[j];
    }
    acc += __shfl_xor_sync(0xFFFFFFFFu, acc, 16);
    acc += __shfl_xor_sync(0xFFFFFFFFu, acc, 8);
    acc += __shfl_xor_sync(0xFFFFFFFFu, acc, 4);
    acc += __shfl_xor_sync(0xFFFFFFFFu, acc, 2);
    acc += __shfl_xor_sync(0xFFFFFFFFu, acc, 1);
    if (l == 0) {
        float Ukse = acc / d[e] - 0.5f;
        out[2 * K + m] = 1.0f / (1.0f + expf(alpha[e] * Ukse + gamma_e[e]));
    }
}

// ---------------- launch ----------------
extern "C" void kernel_launch(void* const* d_in, const int* in_sizes, int n_in,
                              void* d_out, int out_size) {
    const float* U       = (const float*)d_in[0];   // (S,K)
    const float* W       = (const float*)d_in[1];   // (K,E)
    const float* beta1   = (const float*)d_in[2];   // (K,E)
    const float* beta2   = (const float*)d_in[3];   // (E,1)
    const float* Bm      = (const float*)d_in[4];   // (K,E,K)
    const float* gs      = (const float*)d_in[5];   // (E,2)
    const float* A_emb   = (const float*)d_in[6];   // (E,3)
    const float* gamma_c = (const float*)d_in[7];   // (E,1)
    const float* gamma_e = (const float*)d_in[8];   // (E,1)
    const float* alpha   = (const float*)d_in[9];   // (E,1)
    const float* score   = (const float*)d_in[10];  // (E,1)
    const float* user    = (const float*)d_in[11];  // (K,E)
    const float* q_kn    = (const float*)d_in[12];  // (E,K)
    const float* d       = (const float*)d_in[13];  // (E,1)
    const int*   stu_id  = (const int*)d_in[14];    // scalar
    const int*   kn_id   = (const int*)d_in[15];    // (K,)
    const int*   ex_id   = (const int*)d_in[16];    // (M,)
    float* out = (float*)d_out;

    init_kernel<<<E / 256, 256>>>(U, stu_id, kn_id, gamma_c, d, score);
    for (int step = 0; step < NUM_UPDATE; ++step) {
        pre_kernel<<<E / 8, 256>>>(q_kn, d, score, gs, A_emb);
        big_kernel<<<dim3(NCHUNK, K), 256>>>(Bm, beta1, beta2, W, user);
        post_kernel<<<1, K>>>(out, step);
    }
    predict_kernel<<<M / 8, 256>>>(q_kn, d, alpha, gamma_e, ex_id, out);
}

// round 2
// speedup vs baseline: 1.7523x; 1.7523x over previous
#include <cuda_runtime.h>
#include <math.h>

#define K 128
#define E 4096
#define M 512
#define NUM_UPDATE 3
#define THRESHOLD 0.05f
#define ECHUNK 256
#define NCHUNK (E / ECHUNK)   // 16
#define MAXNZ 64

// ---------------- device scratch ----------------
__device__ int   g_nzidx[MAXNZ * E];     // SoA: g_nzidx[i*E + e] = j-th nonzero col of q_kn row e
__device__ int   g_nzcnt[E];
__device__ float g_Ic[E];
__device__ float g_Zc[E];
__device__ float g_u[K];
__device__ float g_dv[K];
__device__ float g_partial[K * NCHUNK];
__device__ int   g_upd[K];

// ---------------- init: nz lists (warp per e-row), Zc, u0, upd ----------------
// grid = E/8 blocks of 256
__global__ void init_kernel(const float* __restrict__ q_kn,
                            const float* __restrict__ U,
                            const int* __restrict__ stu_id,
                            const int* __restrict__ kn_id,
                            const float* __restrict__ gamma_c,
                            const float* __restrict__ d,
                            const float* __restrict__ score) {
    int tid = threadIdx.x;
    int w = tid >> 5, l = tid & 31;
    int e = blockIdx.x * 8 + w;

    int base = 0;
#pragma unroll
    for (int r = 0; r < 4; r++) {
        int j = r * 32 + l;
        float q = q_kn[(size_t)e * K + j];
        unsigned m = __ballot_sync(0xFFFFFFFFu, q != 0.0f);
        if (q != 0.0f) {
            int pos = base + __popc(m & ((1u << l) - 1u));
            if (pos < MAXNZ) g_nzidx[pos * E + e] = j;
        }
        base += __popc(m);
    }
    if (l == 0) {
        g_nzcnt[e] = base < MAXNZ ? base : MAXNZ;
        float x = (gamma_c[e] / d[e]) * (score[e] - 0.5f);
        g_Zc[e] = 1.0f / (1.0f + expf(x)) - 0.5f;
    }

    if (blockIdx.x == 0) {
        if (tid < K) {
            g_u[tid]   = U[stu_id[0] * K + tid];
            g_upd[tid] = 0;
        }
        __syncthreads();
        if (tid < K) {
            int kn = kn_id[tid];
            if (kn >= 0 && kn < K) g_upd[kn] = 1;
        }
    }
}

// ---------------- per-step prologue: dv, su (sparse), Ic ----------------
// grid = E/256 blocks of 256, thread per e
__global__ void pre_kernel(const float* __restrict__ d,
                           const float* __restrict__ score,
                           const float* __restrict__ gs,
                           const float* __restrict__ A_emb) {
    __shared__ float s_u[K];
    int tid = threadIdx.x;
    if (tid < K) s_u[tid] = g_u[tid];
    __syncthreads();

    int e = blockIdx.x * 256 + tid;
    int cnt = g_nzcnt[e];
    float su = 0.0f;
    for (int i = 0; i < cnt; i++) {
        int j = g_nzidx[i * E + e];
        su += s_u[j];
    }
    float t  = score[e] - su / d[e];
    float yc = expf(-t * t);
    float ic = A_emb[3 * e + 0] * (1.0f - gs[2 * e + 0])
             + A_emb[3 * e + 1] * (1.0f - gs[2 * e + 1])
             + A_emb[3 * e + 2] * yc;
    g_Ic[e] = 1.0f / (1.0f + expf(ic));

    if (blockIdx.x == 0 && tid < K) {
        float dv = s_u[tid] - 0.5f;
        g_dv[tid] = (fabsf(dv) > THRESHOLD) ? dv : 0.0f;
    }
}

// ---------------- big kernel: sparse gather of B ----------------
// grid = (NCHUNK, K), block 256, thread per (k, e)
__global__ __launch_bounds__(256) void big_kernel(const float* __restrict__ Bm,
                                                  const float* __restrict__ beta1,
                                                  const float* __restrict__ beta2,
                                                  const float* __restrict__ W,
                                                  const float* __restrict__ user) {
    int k = blockIdx.y;
    int tid = threadIdx.x;
    int e = blockIdx.x * ECHUNK + tid;

    __shared__ float s_dv[K];
    if (tid < K) s_dv[tid] = g_dv[tid];
    __syncthreads();

    const float* __restrict__ Brow = Bm + ((size_t)k * E + e) * K;
    int cnt = g_nzcnt[e];
    float dot = 0.0f;
    for (int i = 0; i < cnt; i++) {
        int j = g_nzidx[i * E + e];
        if (j != k) dot += __ldg(Brow + j) * s_dv[j];
    }

    // Gkc = sigmoid(-Gsum) - 1
    float gkc = 1.0f / (1.0f + expf(dot)) - 1.0f;
    float wk  = g_Ic[e] * (beta1[k * E + e] * gkc + beta2[e] * g_Zc[e]);
    float v   = user[k * E + e] * W[k * E + e] * wk;

    // deterministic block reduction
    __shared__ float warpacc[8];
    int w = tid >> 5, l = tid & 31;
    v += __shfl_xor_sync(0xFFFFFFFFu, v, 16);
    v += __shfl_xor_sync(0xFFFFFFFFu, v, 8);
    v += __shfl_xor_sync(0xFFFFFFFFu, v, 4);
    v += __shfl_xor_sync(0xFFFFFFFFu, v, 2);
    v += __shfl_xor_sync(0xFFFFFFFFu, v, 1);
    if (l == 0) warpacc[w] = v;
    __syncthreads();
    if (tid == 0) {
        float s = 0.0f;
#pragma unroll
        for (int i = 0; i < 8; i++) s += warpacc[i];
        g_partial[k * NCHUNK + blockIdx.x] = s;
    }
}

// ---------------- per-step epilogue ----------------
__global__ void post_kernel(float* __restrict__ out, int step) {
    int k = threadIdx.x;  // 128 threads
    float s = 0.0f;
#pragma unroll
    for (int c = 0; c < NCHUNK; c++) s += g_partial[k * NCHUNK + c];
    float u_old = g_u[k];
    float u_new = 1.0f / (1.0f + expf(s));   // sigmoid(-s)
    float un = g_upd[k] ? u_new : u_old;
    float dd = un - u_old;

    __shared__ float red[K];
    red[k] = dd * dd;
    __syncthreads();
#pragma unroll
    for (int off = 64; off > 0; off >>= 1) {
        if (k < off) red[k] += red[k + off];
        __syncthreads();
    }
    if (k == 0) out[2 * K + M + step] = sqrtf(red[0]);

    g_u[k] = un;
    if (step == NUM_UPDATE - 2) out[K + k] = un;  // state_2nd_last
    if (step == NUM_UPDATE - 1) out[k]     = un;  // state_last
}

// ---------------- final predict ----------------
// grid = M/256 blocks? use thread per m with sparse dot
__global__ void predict_kernel(const float* __restrict__ d,
                               const float* __restrict__ alpha,
                               const float* __restrict__ gamma_e,
                               const int* __restrict__ ex_id,
                               float* __restrict__ out) {
    __shared__ float s_u[K];
    int tid = threadIdx.x;
    if (tid < K) s_u[tid] = g_u[tid];
    __syncthreads();

    int m = blockIdx.x * 256 + tid;
    if (m < M) {
        int e = ex_id[m];
        int cnt = g_nzcnt[e];
        float acc = 0.0f;
        for (int i = 0; i < cnt; i++) {
            int j = g_nzidx[i * E + e];
            acc += s_u[j];
        }
        float Ukse = acc / d[e] - 0.5f;
        out[2 * K + m] = 1.0f / (1.0f + expf(alpha[e] * Ukse + gamma_e[e]));
    }
}

// ---------------- launch ----------------
extern "C" void kernel_launch(void* const* d_in, const int* in_sizes, int n_in,
                              void* d_out, int out_size) {
    const float* U       = (const float*)d_in[0];   // (S,K)
    const float* W       = (const float*)d_in[1];   // (K,E)
    const float* beta1   = (const float*)d_in[2];   // (K,E)
    const float* beta2   = (const float*)d_in[3];   // (E,1)
    const float* Bm      = (const float*)d_in[4];   // (K,E,K)
    const float* gs      = (const float*)d_in[5];   // (E,2)
    const float* A_emb   = (const float*)d_in[6];   // (E,3)
    const float* gamma_c = (const float*)d_in[7];   // (E,1)
    const float* gamma_e = (const float*)d_in[8];   // (E,1)
    const float* alpha   = (const float*)d_in[9];   // (E,1)
    const float* score   = (const float*)d_in[10];  // (E,1)
    const float* user    = (const float*)d_in[11];  // (K,E)
    const float* q_kn    = (const float*)d_in[12];  // (E,K)
    const float* d       = (const float*)d_in[13];  // (E,1)
    const int*   stu_id  = (const int*)d_in[14];    // scalar
    const int*   kn_id   = (const int*)d_in[15];    // (K,)
    const int*   ex_id   = (const int*)d_in[16];    // (M,)
    float* out = (float*)d_out;

    init_kernel<<<E / 8, 256>>>(q_kn, U, stu_id, kn_id, gamma_c, d, score);
    for (int step = 0; step < NUM_UPDATE; ++step) {
        pre_kernel<<<E / 256, 256>>>(d, score, gs, A_emb);
        big_kernel<<<dim3(NCHUNK, K), 256>>>(Bm, beta1, beta2, W, user);
        post_kernel<<<1, K>>>(out, step);
    }
    predict_kernel<<<(M + 255) / 256, 256>>>(d, alpha, gamma_e, ex_id, out);
}